// round 5
// baseline (speedup 1.0000x reference)
#include <cuda_runtime.h>
#include <math.h>

#define BATCH 128
#define CTX 64
#define HID 128
#define KSLICES 19          // 9 time + 9 dist + 1 hidden
#define KTOT (KSLICES*128)  // 2432
#define GRIDN 128
#define NTHREADS 256

typedef unsigned long long u64;

// Scratch (__device__ globals: allocation-free rule)
__device__ float g_Xagg[BATCH * KTOT];             // [b][k] row-major
__device__ float g_gpart[KSLICES * BATCH * HID];   // per-slice GEMM partials
__device__ unsigned g_bar[2];                      // monotonic grid-barrier counters

// ---- packed f32x2 helpers --------------------------------------------------
__device__ __forceinline__ u64 pack2(float v) {
    u64 r; asm("mov.b64 %0, {%1, %1};" : "=l"(r) : "f"(v)); return r;
}
__device__ __forceinline__ void ffma2(u64& d, u64 a, u64 b) {
    asm("fma.rn.f32x2 %0, %1, %2, %0;" : "+l"(d) : "l"(a), "l"(b));
}
__device__ __forceinline__ u64 fadd2(u64 a, u64 b) {
    u64 r; asm("add.rn.f32x2 %0, %1, %2;" : "=l"(r) : "l"(a), "l"(b)); return r;
}

// ---- replay-safe grid barrier (monotonic counter, never reset) -------------
// Every launch adds exactly GRIDN to each counter, so rounds stay aligned
// across graph replays. release-add / acquire-spin gives cross-block ordering;
// the surrounding __syncthreads extends it to all threads of the block.
__device__ __forceinline__ void grid_barrier(unsigned* ctr) {
    __syncthreads();
    if (threadIdx.x == 0) {
        unsigned prev;
        asm volatile("atom.add.release.gpu.u32 %0, [%1], 1;"
                     : "=r"(prev) : "l"(ctr) : "memory");
        unsigned target = prev - (prev & (GRIDN - 1)) + GRIDN;
        unsigned cur;
        do {
            asm volatile("ld.acquire.gpu.u32 %0, [%1];"
                         : "=r"(cur) : "l"(ctr) : "memory");
        } while ((int)(cur - target) < 0);
    }
    __syncthreads();
}

// ---------------------------------------------------------------------------
// Fused persistent kernel: 128 blocks x 256 threads (all co-resident).
//   Phase 1: per-batch slot aggregation (block b = batch b)
//   Phase 2: 152 GEMM tiles (8 n-tiles x 19 K-slices), looped over 128 blocks
//   Phase 3: fold 19 partials + sigmoid
// ---------------------------------------------------------------------------
__global__ __launch_bounds__(NTHREADS, 1)
void fused_strnn(const float* __restrict__ x,     // [B][CTX][128]
                 const int* __restrict__ timec,   // [B][CTX]
                 const int* __restrict__ distc,   // [B][CTX]
                 const void* __restrict__ maskp,  // [B][CTX] int32 OR bytes
                 const float* __restrict__ h,     // [B][128]
                 const float* __restrict__ tw,    // [9][128][128]
                 const float* __restrict__ dw,    // [9][128][128]
                 const float* __restrict__ hw,    // [128][128]
                 float* __restrict__ out)         // [B][128]
{
    __shared__ __align__(16) union SMem {
        struct { u64 sel2[CTX][18]; float red[4][18 * 128]; } p1;  // 46080B
        struct { float As[64 * 128]; float Ws[128 * 16]; } p2;     // 40960B
    } sm;
    __shared__ int s_flag;

    const int bid = blockIdx.x;
    const int tid = threadIdx.x;

    // ---- L2 prefetch of all weights (warms phase 2 staging) ----
    {
        int gt = bid * NTHREADS + tid;             // 32768 threads, 9728 lines
        const char* p = 0;
        if (gt < 4608)       p = (const char*)tw + (size_t)gt * 128;
        else if (gt < 9216)  p = (const char*)dw + (size_t)(gt - 4608) * 128;
        else if (gt < 9728)  p = (const char*)hw + (size_t)(gt - 9216) * 128;
        if (p) asm volatile("prefetch.global.L2 [%0];" :: "l"(p));
    }

    // ===================== Phase 1: slot aggregation ========================
    {
        const int b = bid;
        const int g = tid >> 6;   // ctx group: c in [16g, 16g+16)
        const int q = tid & 63;   // dim pair:  dims 2q, 2q+1

        // Front-issue ALL global loads (one latency round trip, high MLP)
        u64 xv[16];
        {
            const float* xb = x + (size_t)b * CTX * 128 + q * 2;
            #pragma unroll
            for (int cc = 0; cc < 16; cc++)
                xv[cc] = *(const u64*)(xb + (g * 16 + cc) * 128);
        }
        unsigned sniff[8];
        {
            const unsigned* m32 = (const unsigned*)maskp;   // first 2048 words
            #pragma unroll
            for (int i = 0; i < 8; i++) sniff[i] = m32[tid + 256 * i];
        }
        int t_ = 0, d_ = 0; unsigned m_int = 0; unsigned char m_byte = 0;
        if (tid < 128) {
            int c = tid & 63;
            t_ = timec[b * CTX + c];
            d_ = distc[b * CTX + c];
            m_int  = ((const unsigned*)maskp)[b * CTX + c];
            m_byte = ((const unsigned char*)maskp)[b * CTX + c];
        }

        if (tid == 0) s_flag = 0;
        __syncthreads();
        {
            int bad = 0;
            #pragma unroll
            for (int i = 0; i < 8; i++) bad |= (sniff[i] > 1u);
            if (bad) atomicOr(&s_flag, 1);
        }
        __syncthreads();
        const int byte_layout = s_flag;

        // sel2[c][s] = (slot==s) ? (0.5*mask, 0.5*mask) : 0
        if (tid < 128) {
            int c = tid & 63, hf = tid >> 6;
            int m = byte_layout ? (m_byte != 0) : (m_int != 0);
            float w = m ? 0.5f : 0.0f;
            int idx = hf ? d_ : t_;
            u64 wp = pack2(w);
            #pragma unroll
            for (int s = 0; s < 9; s++)
                sm.p1.sel2[c][hf * 9 + s] = (idx == s) ? wp : 0ull;
        }
        __syncthreads();

        u64 acc[18];
        #pragma unroll
        for (int s = 0; s < 18; s++) acc[s] = 0ull;

        #pragma unroll
        for (int cc = 0; cc < 16; cc++) {
            int c = g * 16 + cc;
            u64 xc = xv[cc];
            #pragma unroll
            for (int s = 0; s < 18; s++)
                ffma2(acc[s], sm.p1.sel2[c][s], xc);    // LDS.64 bcast + FFMA2
        }

        #pragma unroll
        for (int s = 0; s < 18; s++)
            *(u64*)&sm.p1.red[g][s * 128 + q * 2] = acc[s];
        __syncthreads();

        float* dstrow = g_Xagg + (size_t)b * KTOT;
        #pragma unroll
        for (int i = tid; i < 18 * 128; i += NTHREADS)
            dstrow[i] = sm.p1.red[0][i] + sm.p1.red[1][i]
                      + sm.p1.red[2][i] + sm.p1.red[3][i];
        if (tid < 128) dstrow[2304 + tid] = h[b * HID + tid];
    }

    grid_barrier(&g_bar[0]);

    // ===================== Phase 2: split-K GEMM ============================
    for (int tile = bid; tile < 8 * KSLICES; tile += GRIDN) {
        const int ntile = tile & 7;
        const int ks    = tile >> 3;
        const int half  = tid >> 7;
        const int row   = tid & 127;

        const float* Wsrc;
        if (ks < 9)       Wsrc = tw + (size_t)ks * 16384;
        else if (ks < 18) Wsrc = dw + (size_t)(ks - 9) * 16384;
        else              Wsrc = hw;

        __syncthreads();   // protect smem reuse (phase1 union / prior tile)
        const int j0 = ntile * 16;
        {
            int k = tid >> 1, off = (tid & 1) * 8;
            const float4* src = (const float4*)(Wsrc + k * 128 + j0 + off);
            float4* dst = (float4*)(sm.p2.Ws + k * 16 + off);
            dst[0] = src[0];
            dst[1] = src[1];
        }

        u64 acc[8];
        #pragma unroll
        for (int i = 0; i < 8; i++) acc[i] = 0ull;

        const float* Abase = g_Xagg + ks * 128;

        #pragma unroll
        for (int c = 0; c < 2; c++) {
            __syncthreads();
            // stage A chunk, XOR-swizzled: conflict-free STS and LDS
            #pragma unroll
            for (int i = 0; i < 32; i++) {
                int idx = i * 256 + tid;
                int kf = idx & 63;
                int bb = idx >> 6;
                int hh = kf >> 5, kk = kf & 31;
                int kglob = hh * 64 + c * 32 + kk;
                sm.p2.As[kf * 128 + (bb ^ kk)] =
                    Abase[(size_t)bb * KTOT + kglob];
            }
            __syncthreads();

            const float* Arow = sm.p2.As + half * 32 * 128;
            const float* Wrow = sm.p2.Ws + (half * 64 + c * 32) * 16;
            #pragma unroll 8
            for (int kk = 0; kk < 32; kk++) {
                u64 a2 = pack2(Arow[kk * 128 + (row ^ kk)]);
                const double2* w = (const double2*)(Wrow + kk * 16);
                double2 w0 = w[0], w1 = w[1], w2 = w[2], w3 = w[3];
                ffma2(acc[0], a2, __double_as_longlong(w0.x));
                ffma2(acc[1], a2, __double_as_longlong(w0.y));
                ffma2(acc[2], a2, __double_as_longlong(w1.x));
                ffma2(acc[3], a2, __double_as_longlong(w1.y));
                ffma2(acc[4], a2, __double_as_longlong(w2.x));
                ffma2(acc[5], a2, __double_as_longlong(w2.y));
                ffma2(acc[6], a2, __double_as_longlong(w3.x));
                ffma2(acc[7], a2, __double_as_longlong(w3.y));
            }
        }

        __syncthreads();
        u64* Cs = (u64*)sm.p2.As;   // alias after mainloop
        if (half) {
            u64* cdst = Cs + row * 8;
            #pragma unroll
            for (int i = 0; i < 8; i++) cdst[i] = acc[i];
        }
        __syncthreads();
        if (!half) {
            const u64* csrc = Cs + row * 8;
            u64* dst = (u64*)(g_gpart + ((size_t)ks * BATCH + row) * HID + j0);
            #pragma unroll
            for (int i = 0; i < 8; i++) dst[i] = fadd2(acc[i], csrc[i]);
        }
    }

    grid_barrier(&g_bar[1]);

    // ===================== Phase 3: fold + sigmoid ==========================
    {
        int i = bid * NTHREADS + tid;
        if (i < BATCH * HID) {
            float v = 0.0f;
            #pragma unroll
            for (int ks = 0; ks < KSLICES; ks++)
                v += g_gpart[ks * (BATCH * HID) + i];
            out[i] = 1.0f / (1.0f + expf(-v));
        }
    }
}

// ---------------------------------------------------------------------------
extern "C" void kernel_launch(void* const* d_in, const int* in_sizes, int n_in,
                              void* d_out, int out_size)
{
    const float* x    = (const float*)d_in[0];
    const int*   tc   = (const int*)  d_in[1];
    const int*   dc   = (const int*)  d_in[2];
    const void*  mask = (const void*) d_in[3];
    const float* h    = (const float*)d_in[4];
    const float* tw   = (const float*)d_in[5];
    const float* dw   = (const float*)d_in[6];
    const float* hw   = (const float*)d_in[7];
    float* out = (float*)d_out;

    fused_strnn<<<GRIDN, NTHREADS>>>(x, tc, dc, mask, h, tw, dw, hw, out);
}